// round 12
// baseline (speedup 1.0000x reference)
#include <cuda_runtime.h>
#include <cuda_bf16.h>

// out[g, :] = sum over rows r with batch[r]==g of x[r, :]
// (softmax over a size-1 axis == 1.0 -> W, b mathematically dead).
// x: [N, 128] fp32, batch: [N] int32 SORTED, out: [10000, 128] fp32.
//
// Inputs identified BY ELEMENT COUNT (robust to metadata ordering).
//
// CONVERGED CONFIG (R10, best measured: 80.4us total, 82.3% DRAM,
// 6.5 TB/s, occ 95.5%, regs 32):
//  - static contiguous per-warp row ranges (no atomics: R9 showed dynamic
//    stealing's serial chunk-head latency kills outstanding-load count)
//  - grid = EXACTLY 2.0 waves at the regs=32 / 8-blocks-per-SM residency
//    limit (2 waves beats 1.65 unaligned [88.6us] and 4 fine waves [83.9us])
//  - register run-length accumulate over sorted ids; flush via
//    red.global.add.v4.f32 at segment boundaries (~1.6 flushes/warp)
//  - __ldcs streaming loads for x (zero reuse)
//  - cudaMemsetAsync prologue zeroes the poisoned output
// Achieved 6.4 TB/s effective is at the B300 LTS-path ceiling (~6300 B/cyc,
// path-independent), so no restructure can materially beat this.

#define C    128
#define TX   32
#define TY   8
#define BLOCKS_PER_SM 8
#define WAVES 2

__device__ __forceinline__ void red_add_v4(float* addr, float4 v) {
    asm volatile("red.global.add.v4.f32 [%0], {%1, %2, %3, %4};"
                 :: "l"(addr), "f"(v.x), "f"(v.y), "f"(v.z), "f"(v.w)
                 : "memory");
}

__global__ __launch_bounds__(TX * TY, BLOCKS_PER_SM)
void segsum_kernel(const float4* __restrict__ x4,     // [N, 32] float4 view
                   const int* __restrict__ batch,     // [N] int32 sorted
                   float* __restrict__ out,           // [G, 128]
                   int N, int G, int rowsPerWarp) {
    const int tx = threadIdx.x;                       // column group
    const int wid = blockIdx.x * TY + threadIdx.y;    // flat warp id

    int r0 = wid * rowsPerWarp;
    if (r0 >= N) return;
    int rend = min(r0 + rowsPerWarp, N);

    float4 acc = make_float4(0.f, 0.f, 0.f, 0.f);
    int cur = __ldg(&batch[r0]);        // uniform across warp -> broadcast

    #pragma unroll 4
    for (int r = r0; r < rend; ++r) {
        int b = __ldg(&batch[r]);               // uniform broadcast load
        float4 v = __ldcs(&x4[(size_t)r * (C / 4) + tx]);  // streaming load
        if (b != cur) {
            int g = min(max(cur, 0), G - 1);    // defensive clamp
            red_add_v4(out + (size_t)g * C + tx * 4, acc);
            acc = make_float4(0.f, 0.f, 0.f, 0.f);
            cur = b;
        }
        acc.x += v.x; acc.y += v.y; acc.z += v.z; acc.w += v.w;
    }
    int g = min(max(cur, 0), G - 1);
    red_add_v4(out + (size_t)g * C + tx * 4, acc);
}

extern "C" void kernel_launch(void* const* d_in, const int* in_sizes, int n_in,
                              void* d_out, int out_size) {
    // --- identify inputs by element count (robust to metadata ordering) ---
    int xi = 0;
    long long best = -1;
    for (int i = 0; i < n_in; ++i)
        if ((long long)in_sizes[i] > best) { best = in_sizes[i]; xi = i; }
    const int N = in_sizes[xi] / C;
    int bi = -1;
    for (int i = 0; i < n_in; ++i)
        if (i != xi && in_sizes[i] == N) { bi = i; break; }
    if (bi < 0) bi = (xi == 1) ? 0 : 1;

    const float* x     = (const float*)d_in[xi];
    const int*   batch = (const int*)d_in[bi];
    float* out = (float*)d_out;
    const int G = out_size / C;

    // Zero the poisoned output (atomics accumulate into it).
    cudaMemsetAsync(out, 0, (size_t)out_size * sizeof(float));

    static int smCount = 0;
    if (smCount == 0) {
        if (cudaDeviceGetAttribute(&smCount, cudaDevAttrMultiProcessorCount, 0)
                != cudaSuccess || smCount <= 0)
            smCount = 148;
    }
    const int grid = smCount * BLOCKS_PER_SM * WAVES;        // 2368 on 148 SMs
    const int totalWarps = grid * TY;
    const int rowsPerWarp = (N + totalWarps - 1) / totalWarps;   // 53 for 1e6

    dim3 block(TX, TY);
    segsum_kernel<<<grid, block>>>((const float4*)x, batch, out,
                                   N, G, rowsPerWarp);
}

// round 13
// speedup vs baseline: 1.0078x; 1.0078x over previous
#include <cuda_runtime.h>
#include <cuda_bf16.h>

// out[g, :] = sum over rows r with batch[r]==g of x[r, :]
// (softmax over a size-1 axis == 1.0 -> W, b mathematically dead).
// x: [N, 128] fp32, batch: [N] int32 SORTED, out: [10000, 128] fp32.
//
// Inputs identified BY ELEMENT COUNT (robust to metadata ordering).
//
// CONVERGED CONFIG (best measured: 80.4us total; 82.3% DRAM, 6.5 TB/s,
// occ 95.5%, regs 32; byte-identical rerun 82.4us => +/-2us noise band):
//  - static contiguous per-warp row ranges (no atomics: dynamic stealing's
//    serial chunk-head latency kills outstanding-load count — measured R9)
//  - grid = EXACTLY 2.0 waves at the regs=32 / 8-blocks-per-SM residency
//    limit (2 waves beats 1.65 unaligned [88.6us] and 4 fine waves [83.9us])
//  - register run-length accumulate over sorted ids; flush via
//    red.global.add.v4.f32 at segment boundaries (~1.6 flushes/warp)
//  - __ldcs streaming loads for x (zero reuse)
//  - cudaMemsetAsync prologue zeroes the poisoned output (~0.4us)
// Achieved 6.4 TB/s effective is at the B300 LTS-path ceiling (~6300 B/cyc,
// path-independent), so no restructure can materially beat this.

#define C    128
#define TX   32
#define TY   8
#define BLOCKS_PER_SM 8
#define WAVES 2

__device__ __forceinline__ void red_add_v4(float* addr, float4 v) {
    asm volatile("red.global.add.v4.f32 [%0], {%1, %2, %3, %4};"
                 :: "l"(addr), "f"(v.x), "f"(v.y), "f"(v.z), "f"(v.w)
                 : "memory");
}

__global__ __launch_bounds__(TX * TY, BLOCKS_PER_SM)
void segsum_kernel(const float4* __restrict__ x4,     // [N, 32] float4 view
                   const int* __restrict__ batch,     // [N] int32 sorted
                   float* __restrict__ out,           // [G, 128]
                   int N, int G, int rowsPerWarp) {
    const int tx = threadIdx.x;                       // column group
    const int wid = blockIdx.x * TY + threadIdx.y;    // flat warp id

    int r0 = wid * rowsPerWarp;
    if (r0 >= N) return;
    int rend = min(r0 + rowsPerWarp, N);

    float4 acc = make_float4(0.f, 0.f, 0.f, 0.f);
    int cur = __ldg(&batch[r0]);        // uniform across warp -> broadcast

    #pragma unroll 4
    for (int r = r0; r < rend; ++r) {
        int b = __ldg(&batch[r]);               // uniform broadcast load
        float4 v = __ldcs(&x4[(size_t)r * (C / 4) + tx]);  // streaming load
        if (b != cur) {
            int g = min(max(cur, 0), G - 1);    // defensive clamp
            red_add_v4(out + (size_t)g * C + tx * 4, acc);
            acc = make_float4(0.f, 0.f, 0.f, 0.f);
            cur = b;
        }
        acc.x += v.x; acc.y += v.y; acc.z += v.z; acc.w += v.w;
    }
    int g = min(max(cur, 0), G - 1);
    red_add_v4(out + (size_t)g * C + tx * 4, acc);
}

extern "C" void kernel_launch(void* const* d_in, const int* in_sizes, int n_in,
                              void* d_out, int out_size) {
    // --- identify inputs by element count (robust to metadata ordering) ---
    int xi = 0;
    long long best = -1;
    for (int i = 0; i < n_in; ++i)
        if ((long long)in_sizes[i] > best) { best = in_sizes[i]; xi = i; }
    const int N = in_sizes[xi] / C;
    int bi = -1;
    for (int i = 0; i < n_in; ++i)
        if (i != xi && in_sizes[i] == N) { bi = i; break; }
    if (bi < 0) bi = (xi == 1) ? 0 : 1;

    const float* x     = (const float*)d_in[xi];
    const int*   batch = (const int*)d_in[bi];
    float* out = (float*)d_out;
    const int G = out_size / C;

    // Zero the poisoned output (atomics accumulate into it).
    cudaMemsetAsync(out, 0, (size_t)out_size * sizeof(float));

    static int smCount = 0;
    if (smCount == 0) {
        if (cudaDeviceGetAttribute(&smCount, cudaDevAttrMultiProcessorCount, 0)
                != cudaSuccess || smCount <= 0)
            smCount = 148;
    }
    const int grid = smCount * BLOCKS_PER_SM * WAVES;        // 2 full waves
    const int totalWarps = grid * TY;
    const int rowsPerWarp = (N + totalWarps - 1) / totalWarps;

    dim3 block(TX, TY);
    segsum_kernel<<<grid, block>>>((const float4*)x, batch, out,
                                   N, G, rowsPerWarp);
}

// round 14
// speedup vs baseline: 1.0251x; 1.0171x over previous
#include <cuda_runtime.h>
#include <cuda_bf16.h>

// out[g, :] = sum over rows r with batch[r]==g of x[r, :]
// (softmax over a size-1 axis == 1.0 -> W, b mathematically dead).
// x: [N, 128] fp32, batch: [N] int32 SORTED, out: [10000, 128] fp32.
//
// Inputs identified BY ELEMENT COUNT (robust to metadata ordering).
//
// FINAL CONVERGED CONFIG (best 80.4us; reruns 82.4/81.8 => +/-1us noise):
//  - static contiguous per-warp row ranges (no atomics: dynamic stealing's
//    serial chunk-head latency kills outstanding-load count — measured R9)
//  - grid = EXACTLY 2.0 waves at the regs=32 / 8-blocks-per-SM residency
//    limit (beats 1.65 unaligned waves [88.6us] and 4 fine waves [83.9us])
//  - register run-length accumulate over sorted ids; flush via
//    red.global.add.v4.f32 at segment boundaries (~1.6 flushes/warp)
//  - __ldcs streaming loads for x (zero reuse)
//  - cudaMemsetAsync prologue zeroes the poisoned output
// Traffic floor: 521.5 MB at the measured ~6.5 TB/s chip stream ceiling
// = 80.2us; best measured total = 80.4us -> executing at the memory floor.

#define C    128
#define TX   32
#define TY   8
#define BLOCKS_PER_SM 8
#define WAVES 2

__device__ __forceinline__ void red_add_v4(float* addr, float4 v) {
    asm volatile("red.global.add.v4.f32 [%0], {%1, %2, %3, %4};"
                 :: "l"(addr), "f"(v.x), "f"(v.y), "f"(v.z), "f"(v.w)
                 : "memory");
}

__global__ __launch_bounds__(TX * TY, BLOCKS_PER_SM)
void segsum_kernel(const float4* __restrict__ x4,     // [N, 32] float4 view
                   const int* __restrict__ batch,     // [N] int32 sorted
                   float* __restrict__ out,           // [G, 128]
                   int N, int G, int rowsPerWarp) {
    const int tx = threadIdx.x;                       // column group
    const int wid = blockIdx.x * TY + threadIdx.y;    // flat warp id

    int r0 = wid * rowsPerWarp;
    if (r0 >= N) return;
    int rend = min(r0 + rowsPerWarp, N);

    float4 acc = make_float4(0.f, 0.f, 0.f, 0.f);
    int cur = __ldg(&batch[r0]);        // uniform across warp -> broadcast

    #pragma unroll 4
    for (int r = r0; r < rend; ++r) {
        int b = __ldg(&batch[r]);               // uniform broadcast load
        float4 v = __ldcs(&x4[(size_t)r * (C / 4) + tx]);  // streaming load
        if (b != cur) {
            int g = min(max(cur, 0), G - 1);    // defensive clamp
            red_add_v4(out + (size_t)g * C + tx * 4, acc);
            acc = make_float4(0.f, 0.f, 0.f, 0.f);
            cur = b;
        }
        acc.x += v.x; acc.y += v.y; acc.z += v.z; acc.w += v.w;
    }
    int g = min(max(cur, 0), G - 1);
    red_add_v4(out + (size_t)g * C + tx * 4, acc);
}

extern "C" void kernel_launch(void* const* d_in, const int* in_sizes, int n_in,
                              void* d_out, int out_size) {
    // --- identify inputs by element count (robust to metadata ordering) ---
    int xi = 0;
    long long best = -1;
    for (int i = 0; i < n_in; ++i)
        if ((long long)in_sizes[i] > best) { best = in_sizes[i]; xi = i; }
    const int N = in_sizes[xi] / C;
    int bi = -1;
    for (int i = 0; i < n_in; ++i)
        if (i != xi && in_sizes[i] == N) { bi = i; break; }
    if (bi < 0) bi = (xi == 1) ? 0 : 1;

    const float* x     = (const float*)d_in[xi];
    const int*   batch = (const int*)d_in[bi];
    float* out = (float*)d_out;
    const int G = out_size / C;

    // Zero the poisoned output (atomics accumulate into it).
    cudaMemsetAsync(out, 0, (size_t)out_size * sizeof(float));

    static int smCount = 0;
    if (smCount == 0) {
        if (cudaDeviceGetAttribute(&smCount, cudaDevAttrMultiProcessorCount, 0)
                != cudaSuccess || smCount <= 0)
            smCount = 148;
    }
    const int grid = smCount * BLOCKS_PER_SM * WAVES;        // 2 full waves
    const int totalWarps = grid * TY;
    const int rowsPerWarp = (N + totalWarps - 1) / totalWarps;

    dim3 block(TX, TY);
    segsum_kernel<<<grid, block>>>((const float4*)x, batch, out,
                                   N, G, rowsPerWarp);
}